// round 4
// baseline (speedup 1.0000x reference)
#include <cuda_runtime.h>

#define NPTS 1024
#define MAXB 4096
#define WEIGHT_THRESH 0.5f
#define EPS_W 1e-5f

// 16 partial sums per batch: W, Sx[3], Sy[3], M[3][3]
__device__ float g_partials[MAXB * 16];

// ---------------------------------------------------------------------------
// Kernel 1: streaming reduction. One block per batch, 256 threads, 4 pts/thr.
// ---------------------------------------------------------------------------
__global__ __launch_bounds__(256, 8)
void wproc_reduce(const float* __restrict__ src,
                  const float* __restrict__ tgt,
                  const float* __restrict__ wgt)
{
    const int b   = blockIdx.x;
    const int tid = threadIdx.x;

    const float4* s4 = (const float4*)(src + (size_t)b * NPTS * 3);
    const float4* t4 = (const float4*)(tgt + (size_t)b * NPTS * 3);
    const float4* w4 = (const float4*)(wgt + (size_t)b * NPTS);

    float4 wv = w4[tid];
    float4 a0 = s4[3 * tid + 0];
    float4 a1 = s4[3 * tid + 1];
    float4 a2 = s4[3 * tid + 2];
    float4 c0 = t4[3 * tid + 0];
    float4 c1 = t4[3 * tid + 1];
    float4 c2 = t4[3 * tid + 2];

    float ws[4];
    ws[0] = (wv.x < WEIGHT_THRESH) ? 0.0f : wv.x;
    ws[1] = (wv.y < WEIGHT_THRESH) ? 0.0f : wv.y;
    ws[2] = (wv.z < WEIGHT_THRESH) ? 0.0f : wv.z;
    ws[3] = (wv.w < WEIGHT_THRESH) ? 0.0f : wv.w;

    float px[4][3] = {{a0.x, a0.y, a0.z},
                      {a0.w, a1.x, a1.y},
                      {a1.z, a1.w, a2.x},
                      {a2.y, a2.z, a2.w}};
    float py[4][3] = {{c0.x, c0.y, c0.z},
                      {c0.w, c1.x, c1.y},
                      {c1.z, c1.w, c2.x},
                      {c2.y, c2.z, c2.w}};

    float acc[16];
    #pragma unroll
    for (int k = 0; k < 16; k++) acc[k] = 0.0f;

    #pragma unroll
    for (int k = 0; k < 4; k++) {
        float w = ws[k];
        float x0 = px[k][0], x1 = px[k][1], x2 = px[k][2];
        float y0 = py[k][0], y1 = py[k][1], y2 = py[k][2];
        acc[0] += w;
        acc[1] += w * x0;  acc[2] += w * x1;  acc[3] += w * x2;
        float wy0 = w * y0, wy1 = w * y1, wy2 = w * y2;
        acc[4] += wy0;     acc[5] += wy1;     acc[6] += wy2;
        acc[7]  += x0 * wy0;  acc[8]  += x0 * wy1;  acc[9]  += x0 * wy2;
        acc[10] += x1 * wy0;  acc[11] += x1 * wy1;  acc[12] += x1 * wy2;
        acc[13] += x2 * wy0;  acc[14] += x2 * wy1;  acc[15] += x2 * wy2;
    }

    // 2 butterfly rounds: lanes 0-7 then hold the 4-lane-group sums
    #pragma unroll
    for (int k = 0; k < 16; k++) {
        acc[k] += __shfl_xor_sync(0xffffffffu, acc[k], 16);
        acc[k] += __shfl_xor_sync(0xffffffffu, acc[k], 8);
    }

    __shared__ float sm[64 * 16];   // 8 warps x 8 lanes x 16 accs
    int warp = tid >> 5, lane = tid & 31;
    if (lane < 8) {
        float4* dst = (float4*)&sm[(warp * 8 + lane) * 16];
        dst[0] = make_float4(acc[0],  acc[1],  acc[2],  acc[3]);
        dst[1] = make_float4(acc[4],  acc[5],  acc[6],  acc[7]);
        dst[2] = make_float4(acc[8],  acc[9],  acc[10], acc[11]);
        dst[3] = make_float4(acc[12], acc[13], acc[14], acc[15]);
    }
    __syncthreads();
    if (tid < 16) {
        float s = 0.0f;
        #pragma unroll
        for (int i = 0; i < 64; i++) s += sm[i * 16 + tid];
        g_partials[b * 16 + tid] = s;
    }
}

// ---------------------------------------------------------------------------
// Kernel 2: one thread per batch — 3x3 proper SVD (Jacobi on H^T H) -> R, t
// Fast-MUFU rotations with overflow-safe tau clamp.
// ---------------------------------------------------------------------------
__global__ __launch_bounds__(32)
void wproc_svd(float* __restrict__ Rout, float* __restrict__ tout, int B)
{
    int b = blockIdx.x * blockDim.x + threadIdx.x;
    if (b >= B) return;

    const float4* p4 = (const float4*)(g_partials + b * 16);
    float4 q0 = p4[0], q1 = p4[1], q2 = p4[2], q3 = p4[3];
    float tot[16] = {q0.x, q0.y, q0.z, q0.w,
                     q1.x, q1.y, q1.z, q1.w,
                     q2.x, q2.y, q2.z, q2.w,
                     q3.x, q3.y, q3.z, q3.w};

    float W  = tot[0];
    float d  = W + EPS_W;
    float id = __fdividef(1.0f, d);
    float coef = (2.0f * d - W) * id * id * id;

    float Sx[3] = {tot[1], tot[2], tot[3]};
    float Sy[3] = {tot[4], tot[5], tot[6]};
    float H[3][3];
    #pragma unroll
    for (int i = 0; i < 3; i++)
        #pragma unroll
        for (int j = 0; j < 3; j++)
            H[i][j] = tot[7 + i * 3 + j] * id - Sx[i] * Sy[j] * coef;

    float src_c[3] = {Sx[0] * id, Sx[1] * id, Sx[2] * id};
    float tgt_c[3] = {Sy[0] * id, Sy[1] * id, Sy[2] * id};

    // A = H^T H
    float A[3][3];
    #pragma unroll
    for (int i = 0; i < 3; i++)
        #pragma unroll
        for (int j = 0; j < 3; j++) {
            float s = 0.0f;
            #pragma unroll
            for (int k = 0; k < 3; k++) s += H[k][i] * H[k][j];
            A[i][j] = s;
        }

    float V[3][3] = {{1, 0, 0}, {0, 1, 0}, {0, 0, 1}};

    #pragma unroll 1
    for (int sweep = 0; sweep < 5; sweep++) {
        #pragma unroll
        for (int pair = 0; pair < 3; pair++) {
            const int p = (pair == 2) ? 1 : 0;
            const int q = (pair == 0) ? 1 : 2;
            float apq = A[p][q];
            if (fabsf(apq) > 1e-30f) {
                float tau = __fdividef(A[q][q] - A[p][p], 2.0f * apq);
                // Clamp so 1+tau^2 never overflows (inf*rsqrt(inf) = NaN).
                tau = fminf(fmaxf(tau, -1e18f), 1e18f);
                float h   = 1.0f + tau * tau;
                float sq  = h * rsqrtf(h);                 // sqrt(1+tau^2)
                float tt  = __fdividef(copysignf(1.0f, tau),
                                       fabsf(tau) + sq);
                float cc  = rsqrtf(1.0f + tt * tt);
                float ss  = tt * cc;
                #pragma unroll
                for (int k = 0; k < 3; k++) {
                    float akp = A[k][p], akq = A[k][q];
                    A[k][p] = cc * akp - ss * akq;
                    A[k][q] = ss * akp + cc * akq;
                }
                #pragma unroll
                for (int k = 0; k < 3; k++) {
                    float apk = A[p][k], aqk = A[q][k];
                    A[p][k] = cc * apk - ss * aqk;
                    A[q][k] = ss * apk + cc * aqk;
                }
                #pragma unroll
                for (int k = 0; k < 3; k++) {
                    float vkp = V[k][p], vkq = V[k][q];
                    V[k][p] = cc * vkp - ss * vkq;
                    V[k][q] = ss * vkp + cc * vkq;
                }
            }
        }
    }

    // Sort eigenvalues descending
    float eig[3] = {A[0][0], A[1][1], A[2][2]};
    int i0 = 0, i1 = 1, i2 = 2, tmpi;
    if (eig[i0] < eig[i1]) { tmpi = i0; i0 = i1; i1 = tmpi; }
    if (eig[i0] < eig[i2]) { tmpi = i0; i0 = i2; i2 = tmpi; }
    if (eig[i1] < eig[i2]) { tmpi = i1; i1 = i2; i2 = tmpi; }

    float v0[3] = {V[0][i0], V[1][i0], V[2][i0]};
    float v1[3] = {V[0][i1], V[1][i1], V[2][i1]};
    float v2[3] = {v0[1] * v1[2] - v0[2] * v1[1],
                   v0[2] * v1[0] - v0[0] * v1[2],
                   v0[0] * v1[1] - v0[1] * v1[0]};

    float u0[3], u1[3], u2[3];
    #pragma unroll
    for (int i = 0; i < 3; i++)
        u0[i] = H[i][0] * v0[0] + H[i][1] * v0[1] + H[i][2] * v0[2];
    float rn0 = rsqrtf(u0[0] * u0[0] + u0[1] * u0[1] + u0[2] * u0[2] + 1e-30f);
    u0[0] *= rn0; u0[1] *= rn0; u0[2] *= rn0;

    #pragma unroll
    for (int i = 0; i < 3; i++)
        u1[i] = H[i][0] * v1[0] + H[i][1] * v1[1] + H[i][2] * v1[2];
    float dp = u1[0] * u0[0] + u1[1] * u0[1] + u1[2] * u0[2];
    u1[0] -= dp * u0[0]; u1[1] -= dp * u0[1]; u1[2] -= dp * u0[2];
    float rn1 = rsqrtf(u1[0] * u1[0] + u1[1] * u1[1] + u1[2] * u1[2] + 1e-30f);
    u1[0] *= rn1; u1[1] *= rn1; u1[2] *= rn1;

    u2[0] = u0[1] * u1[2] - u0[2] * u1[1];
    u2[1] = u0[2] * u1[0] - u0[0] * u1[2];
    u2[2] = u0[0] * u1[1] - u0[1] * u1[0];

    // R = V * U^T
    float R[3][3];
    #pragma unroll
    for (int i = 0; i < 3; i++)
        #pragma unroll
        for (int j = 0; j < 3; j++)
            R[i][j] = v0[i] * u0[j] + v1[i] * u1[j] + v2[i] * u2[j];

    float t[3];
    #pragma unroll
    for (int i = 0; i < 3; i++)
        t[i] = tgt_c[i] - (R[i][0] * src_c[0] + R[i][1] * src_c[1] + R[i][2] * src_c[2]);

    float* Rb = Rout + (size_t)b * 9;
    #pragma unroll
    for (int i = 0; i < 3; i++)
        #pragma unroll
        for (int j = 0; j < 3; j++)
            Rb[i * 3 + j] = R[i][j];
    float* tb = tout + (size_t)b * 3;
    tb[0] = t[0]; tb[1] = t[1]; tb[2] = t[2];
}

extern "C" void kernel_launch(void* const* d_in, const int* in_sizes, int n_in,
                              void* d_out, int out_size)
{
    const float* src = (const float*)d_in[0];
    const float* tgt = (const float*)d_in[1];
    const float* w   = (const float*)d_in[2];
    int B = in_sizes[2] / NPTS;
    float* Rout = (float*)d_out;
    float* tout = Rout + (size_t)B * 9;
    wproc_reduce<<<B, 256>>>(src, tgt, w);
    wproc_svd<<<(B + 31) / 32, 32>>>(Rout, tout, B);
}

// round 5
// speedup vs baseline: 1.2538x; 1.2538x over previous
#include <cuda_runtime.h>

#define NPTS 1024
#define MAXB 4096
#define WEIGHT_THRESH 0.5f
#define EPS_W 1e-5f
#define RED_BLOCKS 296   // 2 resident blocks per SM on 148 SMs

// 16 partial sums per batch: W, Sx[3], Sy[3], M[3][3]
__device__ float g_partials[MAXB * 16];

// ---------------------------------------------------------------------------
// Kernel 1: persistent streaming reduction. Each block loops over batches
// stride gridDim.x, prefetching the next batch's registers so the shuffle/
// smem reduction tail overlaps the next DRAM loads.
// ---------------------------------------------------------------------------
__global__ __launch_bounds__(256)
void wproc_reduce(const float* __restrict__ src,
                  const float* __restrict__ tgt,
                  const float* __restrict__ wgt,
                  int B)
{
    const int tid    = threadIdx.x;
    const int stride = gridDim.x;
    const int warp   = tid >> 5, lane = tid & 31;

    __shared__ float sm[2][8 * 16];

    int b = blockIdx.x;
    if (b >= B) return;

    // Load first batch
    float4 wv, a0, a1, a2, c0, c1, c2;
    {
        const float4* s4 = (const float4*)(src + (size_t)b * NPTS * 3);
        const float4* t4 = (const float4*)(tgt + (size_t)b * NPTS * 3);
        const float4* w4 = (const float4*)(wgt + (size_t)b * NPTS);
        wv = w4[tid];
        a0 = s4[3 * tid + 0]; a1 = s4[3 * tid + 1]; a2 = s4[3 * tid + 2];
        c0 = t4[3 * tid + 0]; c1 = t4[3 * tid + 1]; c2 = t4[3 * tid + 2];
    }

    int p = 0;
    while (true) {
        const int bn = b + stride;
        const bool has_next = (bn < B);

        // Prefetch next batch (loads in flight while we reduce current)
        float4 nwv, na0, na1, na2, nc0, nc1, nc2;
        if (has_next) {
            const float4* s4 = (const float4*)(src + (size_t)bn * NPTS * 3);
            const float4* t4 = (const float4*)(tgt + (size_t)bn * NPTS * 3);
            const float4* w4 = (const float4*)(wgt + (size_t)bn * NPTS);
            nwv = w4[tid];
            na0 = s4[3 * tid + 0]; na1 = s4[3 * tid + 1]; na2 = s4[3 * tid + 2];
            nc0 = t4[3 * tid + 0]; nc1 = t4[3 * tid + 1]; nc2 = t4[3 * tid + 2];
        }

        // ---- compute 16 accumulators for current batch ----
        float ws[4];
        ws[0] = (wv.x < WEIGHT_THRESH) ? 0.0f : wv.x;
        ws[1] = (wv.y < WEIGHT_THRESH) ? 0.0f : wv.y;
        ws[2] = (wv.z < WEIGHT_THRESH) ? 0.0f : wv.z;
        ws[3] = (wv.w < WEIGHT_THRESH) ? 0.0f : wv.w;

        float px[4][3] = {{a0.x, a0.y, a0.z},
                          {a0.w, a1.x, a1.y},
                          {a1.z, a1.w, a2.x},
                          {a2.y, a2.z, a2.w}};
        float py[4][3] = {{c0.x, c0.y, c0.z},
                          {c0.w, c1.x, c1.y},
                          {c1.z, c1.w, c2.x},
                          {c2.y, c2.z, c2.w}};

        float acc[16];
        #pragma unroll
        for (int k = 0; k < 16; k++) acc[k] = 0.0f;

        #pragma unroll
        for (int k = 0; k < 4; k++) {
            float w = ws[k];
            float x0 = px[k][0], x1 = px[k][1], x2 = px[k][2];
            float y0 = py[k][0], y1 = py[k][1], y2 = py[k][2];
            acc[0] += w;
            acc[1] += w * x0;  acc[2] += w * x1;  acc[3] += w * x2;
            float wy0 = w * y0, wy1 = w * y1, wy2 = w * y2;
            acc[4] += wy0;     acc[5] += wy1;     acc[6] += wy2;
            acc[7]  += x0 * wy0;  acc[8]  += x0 * wy1;  acc[9]  += x0 * wy2;
            acc[10] += x1 * wy0;  acc[11] += x1 * wy1;  acc[12] += x1 * wy2;
            acc[13] += x2 * wy0;  acc[14] += x2 * wy1;  acc[15] += x2 * wy2;
        }

        // ---- full 5-round warp butterfly (R2 scheme) ----
        #pragma unroll
        for (int k = 0; k < 16; k++) {
            #pragma unroll
            for (int off = 16; off > 0; off >>= 1)
                acc[k] += __shfl_xor_sync(0xffffffffu, acc[k], off);
        }

        if (lane == 0) {
            #pragma unroll
            for (int k = 0; k < 16; k++) sm[p][warp * 16 + k] = acc[k];
        }
        __syncthreads();
        if (tid < 16) {
            float s = 0.0f;
            #pragma unroll
            for (int w = 0; w < 8; w++) s += sm[p][w * 16 + tid];
            g_partials[b * 16 + tid] = s;
        }

        if (!has_next) break;
        // rotate prefetched registers in
        wv = nwv; a0 = na0; a1 = na1; a2 = na2; c0 = nc0; c1 = nc1; c2 = nc2;
        b = bn;
        p ^= 1;   // double-buffered smem: no second barrier needed
    }
}

// ---------------------------------------------------------------------------
// Kernel 2: one thread per batch — 3x3 proper SVD (Jacobi on H^T H) -> R, t.
// 8 blocks x 512 threads so warps share a warm I$ and hide MUFU latency.
// ---------------------------------------------------------------------------
__global__ __launch_bounds__(512)
void wproc_svd(float* __restrict__ Rout, float* __restrict__ tout, int B)
{
    int b = blockIdx.x * blockDim.x + threadIdx.x;
    if (b >= B) return;

    const float4* p4 = (const float4*)(g_partials + b * 16);
    float4 q0 = p4[0], q1 = p4[1], q2 = p4[2], q3 = p4[3];
    float tot[16] = {q0.x, q0.y, q0.z, q0.w,
                     q1.x, q1.y, q1.z, q1.w,
                     q2.x, q2.y, q2.z, q2.w,
                     q3.x, q3.y, q3.z, q3.w};

    float W  = tot[0];
    float d  = W + EPS_W;
    float id = __fdividef(1.0f, d);
    float coef = (2.0f * d - W) * id * id * id;

    float Sx[3] = {tot[1], tot[2], tot[3]};
    float Sy[3] = {tot[4], tot[5], tot[6]};
    float H[3][3];
    #pragma unroll
    for (int i = 0; i < 3; i++)
        #pragma unroll
        for (int j = 0; j < 3; j++)
            H[i][j] = tot[7 + i * 3 + j] * id - Sx[i] * Sy[j] * coef;

    float src_c[3] = {Sx[0] * id, Sx[1] * id, Sx[2] * id};
    float tgt_c[3] = {Sy[0] * id, Sy[1] * id, Sy[2] * id};

    // A = H^T H
    float A[3][3];
    #pragma unroll
    for (int i = 0; i < 3; i++)
        #pragma unroll
        for (int j = 0; j < 3; j++) {
            float s = 0.0f;
            #pragma unroll
            for (int k = 0; k < 3; k++) s += H[k][i] * H[k][j];
            A[i][j] = s;
        }

    float V[3][3] = {{1, 0, 0}, {0, 1, 0}, {0, 0, 1}};

    #pragma unroll 1
    for (int sweep = 0; sweep < 5; sweep++) {
        #pragma unroll
        for (int pair = 0; pair < 3; pair++) {
            const int p = (pair == 2) ? 1 : 0;
            const int q = (pair == 0) ? 1 : 2;
            float apq = A[p][q];
            if (fabsf(apq) > 1e-30f) {
                float tau = __fdividef(A[q][q] - A[p][p], 2.0f * apq);
                // Clamp so 1+tau^2 never overflows (inf*rsqrt(inf) = NaN).
                tau = fminf(fmaxf(tau, -1e18f), 1e18f);
                float h   = 1.0f + tau * tau;
                float sq  = h * rsqrtf(h);                 // sqrt(1+tau^2)
                float tt  = __fdividef(copysignf(1.0f, tau),
                                       fabsf(tau) + sq);
                float cc  = rsqrtf(1.0f + tt * tt);
                float ss  = tt * cc;
                #pragma unroll
                for (int k = 0; k < 3; k++) {
                    float akp = A[k][p], akq = A[k][q];
                    A[k][p] = cc * akp - ss * akq;
                    A[k][q] = ss * akp + cc * akq;
                }
                #pragma unroll
                for (int k = 0; k < 3; k++) {
                    float apk = A[p][k], aqk = A[q][k];
                    A[p][k] = cc * apk - ss * aqk;
                    A[q][k] = ss * apk + cc * aqk;
                }
                #pragma unroll
                for (int k = 0; k < 3; k++) {
                    float vkp = V[k][p], vkq = V[k][q];
                    V[k][p] = cc * vkp - ss * vkq;
                    V[k][q] = ss * vkp + cc * vkq;
                }
            }
        }
    }

    // Sort eigenvalues descending
    float eig[3] = {A[0][0], A[1][1], A[2][2]};
    int i0 = 0, i1 = 1, i2 = 2, tmpi;
    if (eig[i0] < eig[i1]) { tmpi = i0; i0 = i1; i1 = tmpi; }
    if (eig[i0] < eig[i2]) { tmpi = i0; i0 = i2; i2 = tmpi; }
    if (eig[i1] < eig[i2]) { tmpi = i1; i1 = i2; i2 = tmpi; }

    float v0[3] = {V[0][i0], V[1][i0], V[2][i0]};
    float v1[3] = {V[0][i1], V[1][i1], V[2][i1]};
    float v2[3] = {v0[1] * v1[2] - v0[2] * v1[1],
                   v0[2] * v1[0] - v0[0] * v1[2],
                   v0[0] * v1[1] - v0[1] * v1[0]};

    float u0[3], u1[3], u2[3];
    #pragma unroll
    for (int i = 0; i < 3; i++)
        u0[i] = H[i][0] * v0[0] + H[i][1] * v0[1] + H[i][2] * v0[2];
    float rn0 = rsqrtf(u0[0] * u0[0] + u0[1] * u0[1] + u0[2] * u0[2] + 1e-30f);
    u0[0] *= rn0; u0[1] *= rn0; u0[2] *= rn0;

    #pragma unroll
    for (int i = 0; i < 3; i++)
        u1[i] = H[i][0] * v1[0] + H[i][1] * v1[1] + H[i][2] * v1[2];
    float dp = u1[0] * u0[0] + u1[1] * u0[1] + u1[2] * u0[2];
    u1[0] -= dp * u0[0]; u1[1] -= dp * u0[1]; u1[2] -= dp * u0[2];
    float rn1 = rsqrtf(u1[0] * u1[0] + u1[1] * u1[1] + u1[2] * u1[2] + 1e-30f);
    u1[0] *= rn1; u1[1] *= rn1; u1[2] *= rn1;

    u2[0] = u0[1] * u1[2] - u0[2] * u1[1];
    u2[1] = u0[2] * u1[0] - u0[0] * u1[2];
    u2[2] = u0[0] * u1[1] - u0[1] * u1[0];

    // R = V * U^T
    float R[3][3];
    #pragma unroll
    for (int i = 0; i < 3; i++)
        #pragma unroll
        for (int j = 0; j < 3; j++)
            R[i][j] = v0[i] * u0[j] + v1[i] * u1[j] + v2[i] * u2[j];

    float t[3];
    #pragma unroll
    for (int i = 0; i < 3; i++)
        t[i] = tgt_c[i] - (R[i][0] * src_c[0] + R[i][1] * src_c[1] + R[i][2] * src_c[2]);

    float* Rb = Rout + (size_t)b * 9;
    #pragma unroll
    for (int i = 0; i < 3; i++)
        #pragma unroll
        for (int j = 0; j < 3; j++)
            Rb[i * 3 + j] = R[i][j];
    float* tb = tout + (size_t)b * 3;
    tb[0] = t[0]; tb[1] = t[1]; tb[2] = t[2];
}

extern "C" void kernel_launch(void* const* d_in, const int* in_sizes, int n_in,
                              void* d_out, int out_size)
{
    const float* src = (const float*)d_in[0];
    const float* tgt = (const float*)d_in[1];
    const float* w   = (const float*)d_in[2];
    int B = in_sizes[2] / NPTS;
    float* Rout = (float*)d_out;
    float* tout = Rout + (size_t)B * 9;
    int grid = (B < RED_BLOCKS) ? B : RED_BLOCKS;
    wproc_reduce<<<grid, 256>>>(src, tgt, w, B);
    wproc_svd<<<(B + 511) / 512, 512>>>(Rout, tout, B);
}

// round 6
// speedup vs baseline: 1.5359x; 1.2250x over previous
#include <cuda_runtime.h>

#define NPTS 1024
#define MAXB 4096
#define WEIGHT_THRESH 0.5f
#define EPS_W 1e-5f
#define RED_BLOCKS 296   // 2 resident blocks per SM on 148 SMs

// 16 partial sums per batch: W, Sx[3], Sy[3], M[3][3]
__device__ float g_partials[MAXB * 16];

// ---------------------------------------------------------------------------
// Kernel 1: persistent streaming reduction with register prefetch and a
// reduce-scatter butterfly (16 shuffles instead of 80).
// ---------------------------------------------------------------------------
__global__ __launch_bounds__(256)
void wproc_reduce(const float* __restrict__ src,
                  const float* __restrict__ tgt,
                  const float* __restrict__ wgt,
                  int B)
{
    const int tid    = threadIdx.x;
    const int stride = gridDim.x;
    const int warp   = tid >> 5, lane = tid & 31;

    __shared__ float sm[2][8 * 16];

    int b = blockIdx.x;
    if (b >= B) return;

    float4 wv, a0, a1, a2, c0, c1, c2;
    {
        const float4* s4 = (const float4*)(src + (size_t)b * NPTS * 3);
        const float4* t4 = (const float4*)(tgt + (size_t)b * NPTS * 3);
        const float4* w4 = (const float4*)(wgt + (size_t)b * NPTS);
        wv = w4[tid];
        a0 = s4[3 * tid + 0]; a1 = s4[3 * tid + 1]; a2 = s4[3 * tid + 2];
        c0 = t4[3 * tid + 0]; c1 = t4[3 * tid + 1]; c2 = t4[3 * tid + 2];
    }

    int p = 0;
    while (true) {
        const int bn = b + stride;
        const bool has_next = (bn < B);

        // Prefetch next batch (loads in flight while we reduce current)
        float4 nwv, na0, na1, na2, nc0, nc1, nc2;
        if (has_next) {
            const float4* s4 = (const float4*)(src + (size_t)bn * NPTS * 3);
            const float4* t4 = (const float4*)(tgt + (size_t)bn * NPTS * 3);
            const float4* w4 = (const float4*)(wgt + (size_t)bn * NPTS);
            nwv = w4[tid];
            na0 = s4[3 * tid + 0]; na1 = s4[3 * tid + 1]; na2 = s4[3 * tid + 2];
            nc0 = t4[3 * tid + 0]; nc1 = t4[3 * tid + 1]; nc2 = t4[3 * tid + 2];
        }

        float ws[4];
        ws[0] = (wv.x < WEIGHT_THRESH) ? 0.0f : wv.x;
        ws[1] = (wv.y < WEIGHT_THRESH) ? 0.0f : wv.y;
        ws[2] = (wv.z < WEIGHT_THRESH) ? 0.0f : wv.z;
        ws[3] = (wv.w < WEIGHT_THRESH) ? 0.0f : wv.w;

        float px[4][3] = {{a0.x, a0.y, a0.z},
                          {a0.w, a1.x, a1.y},
                          {a1.z, a1.w, a2.x},
                          {a2.y, a2.z, a2.w}};
        float py[4][3] = {{c0.x, c0.y, c0.z},
                          {c0.w, c1.x, c1.y},
                          {c1.z, c1.w, c2.x},
                          {c2.y, c2.z, c2.w}};

        float acc[16];
        #pragma unroll
        for (int k = 0; k < 16; k++) acc[k] = 0.0f;

        #pragma unroll
        for (int k = 0; k < 4; k++) {
            float w = ws[k];
            float x0 = px[k][0], x1 = px[k][1], x2 = px[k][2];
            float y0 = py[k][0], y1 = py[k][1], y2 = py[k][2];
            acc[0] += w;
            acc[1] += w * x0;  acc[2] += w * x1;  acc[3] += w * x2;
            float wy0 = w * y0, wy1 = w * y1, wy2 = w * y2;
            acc[4] += wy0;     acc[5] += wy1;     acc[6] += wy2;
            acc[7]  += x0 * wy0;  acc[8]  += x0 * wy1;  acc[9]  += x0 * wy2;
            acc[10] += x1 * wy0;  acc[11] += x1 * wy1;  acc[12] += x1 * wy2;
            acc[13] += x2 * wy0;  acc[14] += x2 * wy1;  acc[15] += x2 * wy2;
        }

        // ---- reduce-scatter butterfly: halve active set each round ----
        // Round off=16: keep 8 accs (lane bit4 selects high/low half)
        {
            bool hi = (lane & 16) != 0;
            #pragma unroll
            for (int j = 0; j < 8; j++) {
                float send = hi ? acc[j] : acc[j + 8];
                float keep = hi ? acc[j + 8] : acc[j];
                acc[j] = keep + __shfl_xor_sync(0xffffffffu, send, 16);
            }
        }
        {   // off=8: keep 4
            bool hi = (lane & 8) != 0;
            #pragma unroll
            for (int j = 0; j < 4; j++) {
                float send = hi ? acc[j] : acc[j + 4];
                float keep = hi ? acc[j + 4] : acc[j];
                acc[j] = keep + __shfl_xor_sync(0xffffffffu, send, 8);
            }
        }
        {   // off=4: keep 2
            bool hi = (lane & 4) != 0;
            #pragma unroll
            for (int j = 0; j < 2; j++) {
                float send = hi ? acc[j] : acc[j + 2];
                float keep = hi ? acc[j + 2] : acc[j];
                acc[j] = keep + __shfl_xor_sync(0xffffffffu, send, 4);
            }
        }
        {   // off=2: keep 1
            bool hi = (lane & 2) != 0;
            float send = hi ? acc[0] : acc[1];
            float keep = hi ? acc[1] : acc[0];
            acc[0] = keep + __shfl_xor_sync(0xffffffffu, send, 2);
        }
        // off=1: finish (lanes 2k,2k+1 both hold acc index (lane>>1)&15)
        acc[0] += __shfl_xor_sync(0xffffffffu, acc[0], 1);

        const int accIdx = (lane >> 1) & 15;
        if ((lane & 1) == 0)
            sm[p][warp * 16 + accIdx] = acc[0];
        __syncthreads();
        if (tid < 16) {
            float s = 0.0f;
            #pragma unroll
            for (int w = 0; w < 8; w++) s += sm[p][w * 16 + tid];
            g_partials[b * 16 + tid] = s;
        }

        if (!has_next) break;
        wv = nwv; a0 = na0; a1 = na1; a2 = na2; c0 = nc0; c1 = nc1; c2 = nc2;
        b = bn;
        p ^= 1;   // double-buffered smem: no second barrier needed
    }
}

// ---------------------------------------------------------------------------
// Kernel 2: one thread per batch — 3x3 proper SVD (Jacobi on H^T H) -> R, t.
// 32 blocks x 128 threads: one warp per SMSP across 32 SMs.
// ---------------------------------------------------------------------------
__global__ __launch_bounds__(128)
void wproc_svd(float* __restrict__ Rout, float* __restrict__ tout, int B)
{
    int b = blockIdx.x * blockDim.x + threadIdx.x;
    if (b >= B) return;

    const float4* p4 = (const float4*)(g_partials + b * 16);
    float4 q0 = p4[0], q1 = p4[1], q2 = p4[2], q3 = p4[3];
    float tot[16] = {q0.x, q0.y, q0.z, q0.w,
                     q1.x, q1.y, q1.z, q1.w,
                     q2.x, q2.y, q2.z, q2.w,
                     q3.x, q3.y, q3.z, q3.w};

    float W  = tot[0];
    float d  = W + EPS_W;
    float id = __fdividef(1.0f, d);
    float coef = (2.0f * d - W) * id * id * id;

    float Sx[3] = {tot[1], tot[2], tot[3]};
    float Sy[3] = {tot[4], tot[5], tot[6]};
    float H[3][3];
    #pragma unroll
    for (int i = 0; i < 3; i++)
        #pragma unroll
        for (int j = 0; j < 3; j++)
            H[i][j] = tot[7 + i * 3 + j] * id - Sx[i] * Sy[j] * coef;

    float src_c[3] = {Sx[0] * id, Sx[1] * id, Sx[2] * id};
    float tgt_c[3] = {Sy[0] * id, Sy[1] * id, Sy[2] * id};

    float A[3][3];
    #pragma unroll
    for (int i = 0; i < 3; i++)
        #pragma unroll
        for (int j = 0; j < 3; j++) {
            float s = 0.0f;
            #pragma unroll
            for (int k = 0; k < 3; k++) s += H[k][i] * H[k][j];
            A[i][j] = s;
        }

    float V[3][3] = {{1, 0, 0}, {0, 1, 0}, {0, 0, 1}};

    #pragma unroll 1
    for (int sweep = 0; sweep < 4; sweep++) {
        #pragma unroll
        for (int pair = 0; pair < 3; pair++) {
            const int p = (pair == 2) ? 1 : 0;
            const int q = (pair == 0) ? 1 : 2;
            float apq = A[p][q];
            if (fabsf(apq) > 1e-30f) {
                float tau = __fdividef(A[q][q] - A[p][p], 2.0f * apq);
                // Clamp so 1+tau^2 never overflows (inf*rsqrt(inf) = NaN).
                tau = fminf(fmaxf(tau, -1e18f), 1e18f);
                float h   = 1.0f + tau * tau;
                float sq  = h * rsqrtf(h);                 // sqrt(1+tau^2)
                float tt  = __fdividef(copysignf(1.0f, tau),
                                       fabsf(tau) + sq);
                float cc  = rsqrtf(1.0f + tt * tt);
                float ss  = tt * cc;
                #pragma unroll
                for (int k = 0; k < 3; k++) {
                    float akp = A[k][p], akq = A[k][q];
                    A[k][p] = cc * akp - ss * akq;
                    A[k][q] = ss * akp + cc * akq;
                }
                #pragma unroll
                for (int k = 0; k < 3; k++) {
                    float apk = A[p][k], aqk = A[q][k];
                    A[p][k] = cc * apk - ss * aqk;
                    A[q][k] = ss * apk + cc * aqk;
                }
                #pragma unroll
                for (int k = 0; k < 3; k++) {
                    float vkp = V[k][p], vkq = V[k][q];
                    V[k][p] = cc * vkp - ss * vkq;
                    V[k][q] = ss * vkp + cc * vkq;
                }
            }
        }
    }

    float eig[3] = {A[0][0], A[1][1], A[2][2]};
    int i0 = 0, i1 = 1, i2 = 2, tmpi;
    if (eig[i0] < eig[i1]) { tmpi = i0; i0 = i1; i1 = tmpi; }
    if (eig[i0] < eig[i2]) { tmpi = i0; i0 = i2; i2 = tmpi; }
    if (eig[i1] < eig[i2]) { tmpi = i1; i1 = i2; i2 = tmpi; }

    float v0[3] = {V[0][i0], V[1][i0], V[2][i0]};
    float v1[3] = {V[0][i1], V[1][i1], V[2][i1]};
    float v2[3] = {v0[1] * v1[2] - v0[2] * v1[1],
                   v0[2] * v1[0] - v0[0] * v1[2],
                   v0[0] * v1[1] - v0[1] * v1[0]};

    float u0[3], u1[3], u2[3];
    #pragma unroll
    for (int i = 0; i < 3; i++)
        u0[i] = H[i][0] * v0[0] + H[i][1] * v0[1] + H[i][2] * v0[2];
    float rn0 = rsqrtf(u0[0] * u0[0] + u0[1] * u0[1] + u0[2] * u0[2] + 1e-30f);
    u0[0] *= rn0; u0[1] *= rn0; u0[2] *= rn0;

    #pragma unroll
    for (int i = 0; i < 3; i++)
        u1[i] = H[i][0] * v1[0] + H[i][1] * v1[1] + H[i][2] * v1[2];
    float dp = u1[0] * u0[0] + u1[1] * u0[1] + u1[2] * u0[2];
    u1[0] -= dp * u0[0]; u1[1] -= dp * u0[1]; u1[2] -= dp * u0[2];
    float rn1 = rsqrtf(u1[0] * u1[0] + u1[1] * u1[1] + u1[2] * u1[2] + 1e-30f);
    u1[0] *= rn1; u1[1] *= rn1; u1[2] *= rn1;

    u2[0] = u0[1] * u1[2] - u0[2] * u1[1];
    u2[1] = u0[2] * u1[0] - u0[0] * u1[2];
    u2[2] = u0[0] * u1[1] - u0[1] * u1[0];

    float R[3][3];
    #pragma unroll
    for (int i = 0; i < 3; i++)
        #pragma unroll
        for (int j = 0; j < 3; j++)
            R[i][j] = v0[i] * u0[j] + v1[i] * u1[j] + v2[i] * u2[j];

    float t[3];
    #pragma unroll
    for (int i = 0; i < 3; i++)
        t[i] = tgt_c[i] - (R[i][0] * src_c[0] + R[i][1] * src_c[1] + R[i][2] * src_c[2]);

    float* Rb = Rout + (size_t)b * 9;
    #pragma unroll
    for (int i = 0; i < 3; i++)
        #pragma unroll
        for (int j = 0; j < 3; j++)
            Rb[i * 3 + j] = R[i][j];
    float* tb = tout + (size_t)b * 3;
    tb[0] = t[0]; tb[1] = t[1]; tb[2] = t[2];
}

extern "C" void kernel_launch(void* const* d_in, const int* in_sizes, int n_in,
                              void* d_out, int out_size)
{
    const float* src = (const float*)d_in[0];
    const float* tgt = (const float*)d_in[1];
    const float* w   = (const float*)d_in[2];
    int B = in_sizes[2] / NPTS;
    float* Rout = (float*)d_out;
    float* tout = Rout + (size_t)B * 9;
    int grid = (B < RED_BLOCKS) ? B : RED_BLOCKS;
    wproc_reduce<<<grid, 256>>>(src, tgt, w, B);
    wproc_svd<<<(B + 127) / 128, 128>>>(Rout, tout, B);
}

// round 7
// speedup vs baseline: 1.6633x; 1.0829x over previous
#include <cuda_runtime.h>

#define NPTS 1024
#define WEIGHT_THRESH 0.5f
#define EPS_W 1e-5f
#define RED_BLOCKS 296   // 2 resident blocks per SM on 148 SMs
#define MAX_ITERS 32     // >= ceil(B / RED_BLOCKS); B=4096 -> 14

// ---------------------------------------------------------------------------
// Fused persistent kernel: streaming reduction over all batches assigned to
// this block (register prefetch + reduce-scatter butterfly), partials kept in
// smem; then lanes of warp 0 compute one 3x3 proper SVD each in SIMT.
// ---------------------------------------------------------------------------
__global__ __launch_bounds__(256)
void wproc_fused(const float* __restrict__ src,
                 const float* __restrict__ tgt,
                 const float* __restrict__ wgt,
                 float* __restrict__ Rout,
                 float* __restrict__ tout,
                 int B)
{
    const int tid    = threadIdx.x;
    const int stride = gridDim.x;
    const int warp   = tid >> 5, lane = tid & 31;

    __shared__ float sm[2][8 * 16];
    __shared__ float svd_sm[MAX_ITERS][16];

    int b = blockIdx.x;
    if (b < B) {
        float4 wv, a0, a1, a2, c0, c1, c2;
        {
            const float4* s4 = (const float4*)(src + (size_t)b * NPTS * 3);
            const float4* t4 = (const float4*)(tgt + (size_t)b * NPTS * 3);
            const float4* w4 = (const float4*)(wgt + (size_t)b * NPTS);
            wv = w4[tid];
            a0 = s4[3 * tid + 0]; a1 = s4[3 * tid + 1]; a2 = s4[3 * tid + 2];
            c0 = t4[3 * tid + 0]; c1 = t4[3 * tid + 1]; c2 = t4[3 * tid + 2];
        }

        int p = 0;
        int it = 0;
        while (true) {
            const int bn = b + stride;
            const bool has_next = (bn < B);

            // Prefetch next batch (loads in flight while we reduce current)
            float4 nwv, na0, na1, na2, nc0, nc1, nc2;
            if (has_next) {
                const float4* s4 = (const float4*)(src + (size_t)bn * NPTS * 3);
                const float4* t4 = (const float4*)(tgt + (size_t)bn * NPTS * 3);
                const float4* w4 = (const float4*)(wgt + (size_t)bn * NPTS);
                nwv = w4[tid];
                na0 = s4[3 * tid + 0]; na1 = s4[3 * tid + 1]; na2 = s4[3 * tid + 2];
                nc0 = t4[3 * tid + 0]; nc1 = t4[3 * tid + 1]; nc2 = t4[3 * tid + 2];
            }

            float ws[4];
            ws[0] = (wv.x < WEIGHT_THRESH) ? 0.0f : wv.x;
            ws[1] = (wv.y < WEIGHT_THRESH) ? 0.0f : wv.y;
            ws[2] = (wv.z < WEIGHT_THRESH) ? 0.0f : wv.z;
            ws[3] = (wv.w < WEIGHT_THRESH) ? 0.0f : wv.w;

            float px[4][3] = {{a0.x, a0.y, a0.z},
                              {a0.w, a1.x, a1.y},
                              {a1.z, a1.w, a2.x},
                              {a2.y, a2.z, a2.w}};
            float py[4][3] = {{c0.x, c0.y, c0.z},
                              {c0.w, c1.x, c1.y},
                              {c1.z, c1.w, c2.x},
                              {c2.y, c2.z, c2.w}};

            float acc[16];
            #pragma unroll
            for (int k = 0; k < 16; k++) acc[k] = 0.0f;

            #pragma unroll
            for (int k = 0; k < 4; k++) {
                float w = ws[k];
                float x0 = px[k][0], x1 = px[k][1], x2 = px[k][2];
                float y0 = py[k][0], y1 = py[k][1], y2 = py[k][2];
                acc[0] += w;
                acc[1] += w * x0;  acc[2] += w * x1;  acc[3] += w * x2;
                float wy0 = w * y0, wy1 = w * y1, wy2 = w * y2;
                acc[4] += wy0;     acc[5] += wy1;     acc[6] += wy2;
                acc[7]  += x0 * wy0;  acc[8]  += x0 * wy1;  acc[9]  += x0 * wy2;
                acc[10] += x1 * wy0;  acc[11] += x1 * wy1;  acc[12] += x1 * wy2;
                acc[13] += x2 * wy0;  acc[14] += x2 * wy1;  acc[15] += x2 * wy2;
            }

            // ---- reduce-scatter butterfly: halve active set each round ----
            {
                bool hi = (lane & 16) != 0;
                #pragma unroll
                for (int j = 0; j < 8; j++) {
                    float send = hi ? acc[j] : acc[j + 8];
                    float keep = hi ? acc[j + 8] : acc[j];
                    acc[j] = keep + __shfl_xor_sync(0xffffffffu, send, 16);
                }
            }
            {
                bool hi = (lane & 8) != 0;
                #pragma unroll
                for (int j = 0; j < 4; j++) {
                    float send = hi ? acc[j] : acc[j + 4];
                    float keep = hi ? acc[j + 4] : acc[j];
                    acc[j] = keep + __shfl_xor_sync(0xffffffffu, send, 8);
                }
            }
            {
                bool hi = (lane & 4) != 0;
                #pragma unroll
                for (int j = 0; j < 2; j++) {
                    float send = hi ? acc[j] : acc[j + 2];
                    float keep = hi ? acc[j + 2] : acc[j];
                    acc[j] = keep + __shfl_xor_sync(0xffffffffu, send, 4);
                }
            }
            {
                bool hi = (lane & 2) != 0;
                float send = hi ? acc[0] : acc[1];
                float keep = hi ? acc[1] : acc[0];
                acc[0] = keep + __shfl_xor_sync(0xffffffffu, send, 2);
            }
            acc[0] += __shfl_xor_sync(0xffffffffu, acc[0], 1);

            const int accIdx = (lane >> 1) & 15;
            if ((lane & 1) == 0)
                sm[p][warp * 16 + accIdx] = acc[0];
            __syncthreads();
            if (tid < 16) {
                float s = 0.0f;
                #pragma unroll
                for (int w = 0; w < 8; w++) s += sm[p][w * 16 + tid];
                svd_sm[it][tid] = s;
            }

            if (!has_next) break;
            wv = nwv; a0 = na0; a1 = na1; a2 = na2; c0 = nc0; c1 = nc1; c2 = nc2;
            b = bn;
            it++;
            p ^= 1;   // double-buffered smem: no second barrier needed
        }
    }

    // ---------------- SVD tail: lanes of warp 0, one batch each ------------
    __syncthreads();

    // number of batches this block processed
    int niter = 0;
    if (blockIdx.x < B)
        niter = (B - blockIdx.x + stride - 1) / stride;

    if (tid >= niter) return;   // only warp-0 lanes 0..niter-1 continue

    const int myb = blockIdx.x + tid * stride;

    float tot[16];
    #pragma unroll
    for (int k = 0; k < 16; k++) tot[k] = svd_sm[tid][k];

    float W  = tot[0];
    float d  = W + EPS_W;
    float id = __fdividef(1.0f, d);
    float coef = (2.0f * d - W) * id * id * id;

    float Sx[3] = {tot[1], tot[2], tot[3]};
    float Sy[3] = {tot[4], tot[5], tot[6]};
    float H[3][3];
    #pragma unroll
    for (int i = 0; i < 3; i++)
        #pragma unroll
        for (int j = 0; j < 3; j++)
            H[i][j] = tot[7 + i * 3 + j] * id - Sx[i] * Sy[j] * coef;

    float src_c[3] = {Sx[0] * id, Sx[1] * id, Sx[2] * id};
    float tgt_c[3] = {Sy[0] * id, Sy[1] * id, Sy[2] * id};

    // A = H^T H
    float A[3][3];
    #pragma unroll
    for (int i = 0; i < 3; i++)
        #pragma unroll
        for (int j = 0; j < 3; j++) {
            float s = 0.0f;
            #pragma unroll
            for (int k = 0; k < 3; k++) s += H[k][i] * H[k][j];
            A[i][j] = s;
        }

    float V[3][3] = {{1, 0, 0}, {0, 1, 0}, {0, 0, 1}};

    #pragma unroll 1
    for (int sweep = 0; sweep < 4; sweep++) {
        #pragma unroll
        for (int pair = 0; pair < 3; pair++) {
            const int p2 = (pair == 2) ? 1 : 0;
            const int q2 = (pair == 0) ? 1 : 2;
            float apq = A[p2][q2];
            if (fabsf(apq) > 1e-30f) {
                float tau = __fdividef(A[q2][q2] - A[p2][p2], 2.0f * apq);
                // Clamp so 1+tau^2 never overflows (inf*rsqrt(inf) = NaN).
                tau = fminf(fmaxf(tau, -1e18f), 1e18f);
                float h   = 1.0f + tau * tau;
                float sq  = h * rsqrtf(h);                 // sqrt(1+tau^2)
                float tt  = __fdividef(copysignf(1.0f, tau),
                                       fabsf(tau) + sq);
                float cc  = rsqrtf(1.0f + tt * tt);
                float ss  = tt * cc;
                #pragma unroll
                for (int k = 0; k < 3; k++) {
                    float akp = A[k][p2], akq = A[k][q2];
                    A[k][p2] = cc * akp - ss * akq;
                    A[k][q2] = ss * akp + cc * akq;
                }
                #pragma unroll
                for (int k = 0; k < 3; k++) {
                    float apk = A[p2][k], aqk = A[q2][k];
                    A[p2][k] = cc * apk - ss * aqk;
                    A[q2][k] = ss * apk + cc * aqk;
                }
                #pragma unroll
                for (int k = 0; k < 3; k++) {
                    float vkp = V[k][p2], vkq = V[k][q2];
                    V[k][p2] = cc * vkp - ss * vkq;
                    V[k][q2] = ss * vkp + cc * vkq;
                }
            }
        }
    }

    // Sort eigenvalues descending
    float eig[3] = {A[0][0], A[1][1], A[2][2]};
    int i0 = 0, i1 = 1, i2 = 2, tmpi;
    if (eig[i0] < eig[i1]) { tmpi = i0; i0 = i1; i1 = tmpi; }
    if (eig[i0] < eig[i2]) { tmpi = i0; i0 = i2; i2 = tmpi; }
    if (eig[i1] < eig[i2]) { tmpi = i1; i1 = i2; i2 = tmpi; }

    float v0[3] = {V[0][i0], V[1][i0], V[2][i0]};
    float v1[3] = {V[0][i1], V[1][i1], V[2][i1]};
    float v2[3] = {v0[1] * v1[2] - v0[2] * v1[1],
                   v0[2] * v1[0] - v0[0] * v1[2],
                   v0[0] * v1[1] - v0[1] * v1[0]};

    float u0[3], u1[3], u2[3];
    #pragma unroll
    for (int i = 0; i < 3; i++)
        u0[i] = H[i][0] * v0[0] + H[i][1] * v0[1] + H[i][2] * v0[2];
    float rn0 = rsqrtf(u0[0] * u0[0] + u0[1] * u0[1] + u0[2] * u0[2] + 1e-30f);
    u0[0] *= rn0; u0[1] *= rn0; u0[2] *= rn0;

    #pragma unroll
    for (int i = 0; i < 3; i++)
        u1[i] = H[i][0] * v1[0] + H[i][1] * v1[1] + H[i][2] * v1[2];
    float dp = u1[0] * u0[0] + u1[1] * u0[1] + u1[2] * u0[2];
    u1[0] -= dp * u0[0]; u1[1] -= dp * u0[1]; u1[2] -= dp * u0[2];
    float rn1 = rsqrtf(u1[0] * u1[0] + u1[1] * u1[1] + u1[2] * u1[2] + 1e-30f);
    u1[0] *= rn1; u1[1] *= rn1; u1[2] *= rn1;

    u2[0] = u0[1] * u1[2] - u0[2] * u1[1];
    u2[1] = u0[2] * u1[0] - u0[0] * u1[2];
    u2[2] = u0[0] * u1[1] - u0[1] * u1[0];

    // R = V * U^T
    float R[3][3];
    #pragma unroll
    for (int i = 0; i < 3; i++)
        #pragma unroll
        for (int j = 0; j < 3; j++)
            R[i][j] = v0[i] * u0[j] + v1[i] * u1[j] + v2[i] * u2[j];

    float t[3];
    #pragma unroll
    for (int i = 0; i < 3; i++)
        t[i] = tgt_c[i] - (R[i][0] * src_c[0] + R[i][1] * src_c[1] + R[i][2] * src_c[2]);

    float* Rb = Rout + (size_t)myb * 9;
    #pragma unroll
    for (int i = 0; i < 3; i++)
        #pragma unroll
        for (int j = 0; j < 3; j++)
            Rb[i * 3 + j] = R[i][j];
    float* tb = tout + (size_t)myb * 3;
    tb[0] = t[0]; tb[1] = t[1]; tb[2] = t[2];
}

extern "C" void kernel_launch(void* const* d_in, const int* in_sizes, int n_in,
                              void* d_out, int out_size)
{
    const float* src = (const float*)d_in[0];
    const float* tgt = (const float*)d_in[1];
    const float* w   = (const float*)d_in[2];
    int B = in_sizes[2] / NPTS;
    float* Rout = (float*)d_out;
    float* tout = Rout + (size_t)B * 9;
    int grid = (B < RED_BLOCKS) ? B : RED_BLOCKS;
    wproc_fused<<<grid, 256>>>(src, tgt, w, Rout, tout, B);
}

// round 8
// speedup vs baseline: 1.6935x; 1.0182x over previous
#include <cuda_runtime.h>

#define NPTS 1024
#define WEIGHT_THRESH 0.5f
#define EPS_W 1e-5f
#define RED_BLOCKS 444   // 3 resident blocks per SM on 148 SMs
#define MAX_ITERS 32     // >= ceil(B / RED_BLOCKS); B=4096 -> 10

// ---------------------------------------------------------------------------
// Fused persistent kernel: streaming reduction over all batches assigned to
// this block (register prefetch + reduce-scatter butterfly), partials kept in
// smem; then lanes of warp 0 compute one 3x3 proper SVD each in SIMT.
// ---------------------------------------------------------------------------
__global__ __launch_bounds__(256, 3)
void wproc_fused(const float* __restrict__ src,
                 const float* __restrict__ tgt,
                 const float* __restrict__ wgt,
                 float* __restrict__ Rout,
                 float* __restrict__ tout,
                 int B)
{
    const int tid    = threadIdx.x;
    const int stride = gridDim.x;
    const int warp   = tid >> 5, lane = tid & 31;

    __shared__ float sm[2][8 * 16];
    __shared__ float svd_sm[MAX_ITERS][16];

    int b = blockIdx.x;
    if (b < B) {
        float4 wv, a0, a1, a2, c0, c1, c2;
        {
            const float4* s4 = (const float4*)(src + (size_t)b * NPTS * 3);
            const float4* t4 = (const float4*)(tgt + (size_t)b * NPTS * 3);
            const float4* w4 = (const float4*)(wgt + (size_t)b * NPTS);
            wv = w4[tid];
            a0 = s4[3 * tid + 0]; a1 = s4[3 * tid + 1]; a2 = s4[3 * tid + 2];
            c0 = t4[3 * tid + 0]; c1 = t4[3 * tid + 1]; c2 = t4[3 * tid + 2];
        }

        int p = 0;
        int it = 0;
        while (true) {
            const int bn = b + stride;
            const bool has_next = (bn < B);

            // Prefetch next batch (loads in flight while we reduce current)
            float4 nwv, na0, na1, na2, nc0, nc1, nc2;
            if (has_next) {
                const float4* s4 = (const float4*)(src + (size_t)bn * NPTS * 3);
                const float4* t4 = (const float4*)(tgt + (size_t)bn * NPTS * 3);
                const float4* w4 = (const float4*)(wgt + (size_t)bn * NPTS);
                nwv = w4[tid];
                na0 = s4[3 * tid + 0]; na1 = s4[3 * tid + 1]; na2 = s4[3 * tid + 2];
                nc0 = t4[3 * tid + 0]; nc1 = t4[3 * tid + 1]; nc2 = t4[3 * tid + 2];
            }

            float ws[4];
            ws[0] = (wv.x < WEIGHT_THRESH) ? 0.0f : wv.x;
            ws[1] = (wv.y < WEIGHT_THRESH) ? 0.0f : wv.y;
            ws[2] = (wv.z < WEIGHT_THRESH) ? 0.0f : wv.z;
            ws[3] = (wv.w < WEIGHT_THRESH) ? 0.0f : wv.w;

            float px[4][3] = {{a0.x, a0.y, a0.z},
                              {a0.w, a1.x, a1.y},
                              {a1.z, a1.w, a2.x},
                              {a2.y, a2.z, a2.w}};
            float py[4][3] = {{c0.x, c0.y, c0.z},
                              {c0.w, c1.x, c1.y},
                              {c1.z, c1.w, c2.x},
                              {c2.y, c2.z, c2.w}};

            float acc[16];
            #pragma unroll
            for (int k = 0; k < 16; k++) acc[k] = 0.0f;

            #pragma unroll
            for (int k = 0; k < 4; k++) {
                float w = ws[k];
                float x0 = px[k][0], x1 = px[k][1], x2 = px[k][2];
                float y0 = py[k][0], y1 = py[k][1], y2 = py[k][2];
                acc[0] += w;
                acc[1] += w * x0;  acc[2] += w * x1;  acc[3] += w * x2;
                float wy0 = w * y0, wy1 = w * y1, wy2 = w * y2;
                acc[4] += wy0;     acc[5] += wy1;     acc[6] += wy2;
                acc[7]  += x0 * wy0;  acc[8]  += x0 * wy1;  acc[9]  += x0 * wy2;
                acc[10] += x1 * wy0;  acc[11] += x1 * wy1;  acc[12] += x1 * wy2;
                acc[13] += x2 * wy0;  acc[14] += x2 * wy1;  acc[15] += x2 * wy2;
            }

            // ---- reduce-scatter butterfly: halve active set each round ----
            {
                bool hi = (lane & 16) != 0;
                #pragma unroll
                for (int j = 0; j < 8; j++) {
                    float send = hi ? acc[j] : acc[j + 8];
                    float keep = hi ? acc[j + 8] : acc[j];
                    acc[j] = keep + __shfl_xor_sync(0xffffffffu, send, 16);
                }
            }
            {
                bool hi = (lane & 8) != 0;
                #pragma unroll
                for (int j = 0; j < 4; j++) {
                    float send = hi ? acc[j] : acc[j + 4];
                    float keep = hi ? acc[j + 4] : acc[j];
                    acc[j] = keep + __shfl_xor_sync(0xffffffffu, send, 8);
                }
            }
            {
                bool hi = (lane & 4) != 0;
                #pragma unroll
                for (int j = 0; j < 2; j++) {
                    float send = hi ? acc[j] : acc[j + 2];
                    float keep = hi ? acc[j + 2] : acc[j];
                    acc[j] = keep + __shfl_xor_sync(0xffffffffu, send, 4);
                }
            }
            {
                bool hi = (lane & 2) != 0;
                float send = hi ? acc[0] : acc[1];
                float keep = hi ? acc[1] : acc[0];
                acc[0] = keep + __shfl_xor_sync(0xffffffffu, send, 2);
            }
            acc[0] += __shfl_xor_sync(0xffffffffu, acc[0], 1);

            const int accIdx = (lane >> 1) & 15;
            if ((lane & 1) == 0)
                sm[p][warp * 16 + accIdx] = acc[0];
            __syncthreads();
            if (tid < 16) {
                float s = 0.0f;
                #pragma unroll
                for (int w = 0; w < 8; w++) s += sm[p][w * 16 + tid];
                svd_sm[it][tid] = s;
            }

            if (!has_next) break;
            wv = nwv; a0 = na0; a1 = na1; a2 = na2; c0 = nc0; c1 = nc1; c2 = nc2;
            b = bn;
            it++;
            p ^= 1;   // double-buffered smem: no second barrier needed
        }
    }

    // ---------------- SVD tail: lanes of warp 0, one batch each ------------
    __syncthreads();

    int niter = 0;
    if (blockIdx.x < B)
        niter = (B - blockIdx.x + stride - 1) / stride;

    if (tid >= niter) return;   // only warp-0 lanes 0..niter-1 continue

    const int myb = blockIdx.x + tid * stride;

    float tot[16];
    #pragma unroll
    for (int k = 0; k < 16; k++) tot[k] = svd_sm[tid][k];

    float W  = tot[0];
    float d  = W + EPS_W;
    float id = __fdividef(1.0f, d);
    float coef = (2.0f * d - W) * id * id * id;

    float Sx[3] = {tot[1], tot[2], tot[3]};
    float Sy[3] = {tot[4], tot[5], tot[6]};
    float H[3][3];
    #pragma unroll
    for (int i = 0; i < 3; i++)
        #pragma unroll
        for (int j = 0; j < 3; j++)
            H[i][j] = tot[7 + i * 3 + j] * id - Sx[i] * Sy[j] * coef;

    float src_c[3] = {Sx[0] * id, Sx[1] * id, Sx[2] * id};
    float tgt_c[3] = {Sy[0] * id, Sy[1] * id, Sy[2] * id};

    // A = H^T H
    float A[3][3];
    #pragma unroll
    for (int i = 0; i < 3; i++)
        #pragma unroll
        for (int j = 0; j < 3; j++) {
            float s = 0.0f;
            #pragma unroll
            for (int k = 0; k < 3; k++) s += H[k][i] * H[k][j];
            A[i][j] = s;
        }

    float V[3][3] = {{1, 0, 0}, {0, 1, 0}, {0, 0, 1}};

    #pragma unroll 1
    for (int sweep = 0; sweep < 4; sweep++) {
        #pragma unroll
        for (int pair = 0; pair < 3; pair++) {
            const int p2 = (pair == 2) ? 1 : 0;
            const int q2 = (pair == 0) ? 1 : 2;
            float apq = A[p2][q2];
            if (fabsf(apq) > 1e-30f) {
                float tau = __fdividef(A[q2][q2] - A[p2][p2], 2.0f * apq);
                // Clamp so 1+tau^2 never overflows (inf*rsqrt(inf) = NaN).
                tau = fminf(fmaxf(tau, -1e18f), 1e18f);
                float h   = 1.0f + tau * tau;
                float sq  = h * rsqrtf(h);                 // sqrt(1+tau^2)
                float tt  = __fdividef(copysignf(1.0f, tau),
                                       fabsf(tau) + sq);
                float cc  = rsqrtf(1.0f + tt * tt);
                float ss  = tt * cc;
                #pragma unroll
                for (int k = 0; k < 3; k++) {
                    float akp = A[k][p2], akq = A[k][q2];
                    A[k][p2] = cc * akp - ss * akq;
                    A[k][q2] = ss * akp + cc * akq;
                }
                #pragma unroll
                for (int k = 0; k < 3; k++) {
                    float apk = A[p2][k], aqk = A[q2][k];
                    A[p2][k] = cc * apk - ss * aqk;
                    A[q2][k] = ss * apk + cc * aqk;
                }
                #pragma unroll
                for (int k = 0; k < 3; k++) {
                    float vkp = V[k][p2], vkq = V[k][q2];
                    V[k][p2] = cc * vkp - ss * vkq;
                    V[k][q2] = ss * vkp + cc * vkq;
                }
            }
        }
    }

    // Sort eigenvalues descending
    float eig[3] = {A[0][0], A[1][1], A[2][2]};
    int i0 = 0, i1 = 1, i2 = 2, tmpi;
    if (eig[i0] < eig[i1]) { tmpi = i0; i0 = i1; i1 = tmpi; }
    if (eig[i0] < eig[i2]) { tmpi = i0; i0 = i2; i2 = tmpi; }
    if (eig[i1] < eig[i2]) { tmpi = i1; i1 = i2; i2 = tmpi; }

    float v0[3] = {V[0][i0], V[1][i0], V[2][i0]};
    float v1[3] = {V[0][i1], V[1][i1], V[2][i1]};
    float v2[3] = {v0[1] * v1[2] - v0[2] * v1[1],
                   v0[2] * v1[0] - v0[0] * v1[2],
                   v0[0] * v1[1] - v0[1] * v1[0]};

    float u0[3], u1[3], u2[3];
    #pragma unroll
    for (int i = 0; i < 3; i++)
        u0[i] = H[i][0] * v0[0] + H[i][1] * v0[1] + H[i][2] * v0[2];
    float rn0 = rsqrtf(u0[0] * u0[0] + u0[1] * u0[1] + u0[2] * u0[2] + 1e-30f);
    u0[0] *= rn0; u0[1] *= rn0; u0[2] *= rn0;

    #pragma unroll
    for (int i = 0; i < 3; i++)
        u1[i] = H[i][0] * v1[0] + H[i][1] * v1[1] + H[i][2] * v1[2];
    float dp = u1[0] * u0[0] + u1[1] * u0[1] + u1[2] * u0[2];
    u1[0] -= dp * u0[0]; u1[1] -= dp * u0[1]; u1[2] -= dp * u0[2];
    float rn1 = rsqrtf(u1[0] * u1[0] + u1[1] * u1[1] + u1[2] * u1[2] + 1e-30f);
    u1[0] *= rn1; u1[1] *= rn1; u1[2] *= rn1;

    u2[0] = u0[1] * u1[2] - u0[2] * u1[1];
    u2[1] = u0[2] * u1[0] - u0[0] * u1[2];
    u2[2] = u0[0] * u1[1] - u0[1] * u1[0];

    // R = V * U^T
    float R[3][3];
    #pragma unroll
    for (int i = 0; i < 3; i++)
        #pragma unroll
        for (int j = 0; j < 3; j++)
            R[i][j] = v0[i] * u0[j] + v1[i] * u1[j] + v2[i] * u2[j];

    float t[3];
    #pragma unroll
    for (int i = 0; i < 3; i++)
        t[i] = tgt_c[i] - (R[i][0] * src_c[0] + R[i][1] * src_c[1] + R[i][2] * src_c[2]);

    float* Rb = Rout + (size_t)myb * 9;
    #pragma unroll
    for (int i = 0; i < 3; i++)
        #pragma unroll
        for (int j = 0; j < 3; j++)
            Rb[i * 3 + j] = R[i][j];
    float* tb = tout + (size_t)myb * 3;
    tb[0] = t[0]; tb[1] = t[1]; tb[2] = t[2];
}

extern "C" void kernel_launch(void* const* d_in, const int* in_sizes, int n_in,
                              void* d_out, int out_size)
{
    const float* src = (const float*)d_in[0];
    const float* tgt = (const float*)d_in[1];
    const float* w   = (const float*)d_in[2];
    int B = in_sizes[2] / NPTS;
    float* Rout = (float*)d_out;
    float* tout = Rout + (size_t)B * 9;
    int grid = (B < RED_BLOCKS) ? B : RED_BLOCKS;
    wproc_fused<<<grid, 256>>>(src, tgt, w, Rout, tout, B);
}